// round 15
// baseline (speedup 1.0000x reference)
#include <cuda_runtime.h>
#include <math.h>

#define T 2048
#define N 64
#define F 64
#define A 64
#define NH 8
#define QG 256
#define QH 256
#define DG 256
#define DH 256
#define HZ 16

#define XIN  (F + 2*A*NH)        // 1088
#define HIN  (QG + F + A*NH)     // 832
#define DXIN (F + A*NH)          // 576
#define DHIN (DG + F + A*NH + A) // 896
#define NHA  (NH*A)              // 512

#define GRID1 128
#define NT 256

// output layout: pred, attw, q_gru_n, dec_gru_n, query_n (flattened concat)
#define PRED_SZ   (T*N*A)              // 8388608
#define ATTW_OFF  PRED_SZ
#define ATTW_SZ   (T*NH*N)             // 1048576
#define QGRU_OFF  (ATTW_OFF + ATTW_SZ)
#define DECGRU_OFF (QGRU_OFF + QG)
#define QN_OFF    (DECGRU_OFF + DG)

// ---------------- device scratch (static, allowed) ----------------
__device__ float g_h[2][QG];
__device__ float g_query[NHA];
__device__ float g_attv[NHA];
__device__ float g_hid[QH];
__device__ float g_attw[T * NHA];        // 4 MB
__device__ float g_dec_gru[T][DG];       // 2 MB
__device__ float g_dec_atta[T][NHA];     // 4 MB
__device__ float g_zf[T][DH];            // 2 MB
__device__ float g_fin_h[QG];
__device__ float g_fin_dec[DG];
__device__ float g_fin_q[NHA];
__device__ unsigned g_bar1;
__device__ unsigned g_bar2;

// ---------------- helpers ----------------
__device__ __forceinline__ float wredsum(float v) {
    #pragma unroll
    for (int o = 16; o; o >>= 1) v += __shfl_down_sync(0xffffffffu, v, o);
    return v;
}
__device__ __forceinline__ float sigf(float x) { return 1.0f / (1.0f + expf(-x)); }

// monotonic-counter grid barrier; all CTAs must be co-resident
__device__ __forceinline__ void gbar(unsigned* ctr, unsigned& tgt) {
    __syncthreads();
    if (threadIdx.x == 0) {
        __threadfence();
        atomicAdd(ctr, 1u);
        tgt += GRID1;
        while (*(volatile unsigned*)ctr < tgt) { }
    }
    __syncthreads();
}

// ---------------- init ----------------
__global__ void init_kernel() {
    int tid = threadIdx.x;
    if (tid == 0) { g_bar1 = 0u; g_bar2 = 0u; }
    if (tid < QG)  g_h[0][tid] = 0.0f;
    if (tid < NHA) g_query[tid] = 1.0f;
}

// ---------------- phase 1: recurrent query scan ----------------
__global__ void __launch_bounds__(NT, 1)
phase1_kernel(const float* __restrict__ x_fix, const float* __restrict__ x_att,
              const float* __restrict__ wih, const float* __restrict__ whh,
              const float* __restrict__ bih, const float* __restrict__ bhh,
              const float* __restrict__ qhw, const float* __restrict__ qhb,
              const float* __restrict__ wq)
{
    const int tid  = threadIdx.x, cta = blockIdx.x;
    const int lane = tid & 31,    warp = tid >> 5;
    unsigned tgt = 0;

    __shared__ float att_s[64 * 69];
    __shared__ float q_s[64], aw_s[64], red_s[4 * 64];
    __shared__ float sred[2];
    __shared__ float xin_s[XIN];
    __shared__ float h_s[QG];
    __shared__ float gi_s[2][3], gh_s[2][3];
    __shared__ float p3_s[2][4];

    const int p64 = tid >> 6, j64 = tid & 63;

    for (int t = 0; t < T; ++t) {
        const int cb = t & 1, nb = cb ^ 1;

        // ---- stage 1 (CTAs 0..7): query projection (t>0) + attention for head h ----
        if (cta < NH) {
            const int h = cta;
            const float* at = x_att + (size_t)t * N * A;
            for (int idx = tid; idx < N * A; idx += NT)
                att_s[(idx >> 6) * 69 + (idx & 63)] = at[idx];

            if (t > 0) {
                float acc = 0.0f;
                const float* wqc = wq + h * 64 + j64;
                #pragma unroll 4
                for (int i = p64 * 64; i < p64 * 64 + 64; ++i)
                    acc += __ldcg(&g_hid[i]) * wqc[(size_t)i * NHA];
                red_s[p64 * 64 + j64] = acc;
                __syncthreads();
                if (tid < 64) {
                    float q = red_s[tid] + red_s[64 + tid] + red_s[128 + tid] + red_s[192 + tid];
                    q_s[tid] = q;
                    __stcg(&g_query[h * 64 + tid], q);
                }
            } else {
                if (tid < 64) q_s[tid] = 1.0f;   // initial query = ones (g_query preset)
            }
            __syncthreads();

            // logits (scaled)
            if (tid < 64) {
                float l = 0.0f;
                const float* ar = att_s + tid * 69;
                #pragma unroll 8
                for (int a = 0; a < 64; ++a) l += q_s[a] * ar[a];
                red_s[tid] = l * 0.125f;
            }
            __syncthreads();
            if (tid < 32) {
                float m = fmaxf(red_s[tid], red_s[tid + 32]);
                #pragma unroll
                for (int o = 16; o; o >>= 1) m = fmaxf(m, __shfl_down_sync(0xffffffffu, m, o));
                if (tid == 0) sred[0] = m;
            }
            __syncthreads();
            if (tid < 64) aw_s[tid] = expf(red_s[tid] - sred[0]);
            __syncthreads();
            if (tid < 32) {
                float s = wredsum(aw_s[tid] + aw_s[tid + 32]);
                if (tid == 0) sred[1] = s;
            }
            __syncthreads();
            if (tid < 64) {
                float w = aw_s[tid] / sred[1];
                aw_s[tid] = w;
                g_attw[(size_t)t * NHA + h * 64 + tid] = w;
            }
            __syncthreads();
            // att_v[h, a]
            {
                float acc = 0.0f;
                #pragma unroll 4
                for (int n = p64 * 16; n < p64 * 16 + 16; ++n)
                    acc += aw_s[n] * att_s[n * 69 + j64];
                red_s[p64 * 64 + j64] = acc;
            }
            __syncthreads();
            if (tid < 64)
                __stcg(&g_attv[h * 64 + tid],
                       red_s[tid] + red_s[64 + tid] + red_s[128 + tid] + red_s[192 + tid]);
        }
        gbar(&g_bar1, tgt);

        // ---- stage 2: GRU (2 rows per CTA) ----
        for (int k = tid; k < XIN; k += NT) {
            float v;
            if (k < F)            v = x_fix[t * F + k];
            else if (k < F + NHA) v = __ldcg(&g_attv[k - F]);
            else                  v = __ldcg(&g_query[k - F - NHA]);
            xin_s[k] = v;
        }
        for (int k = tid; k < QG; k += NT) h_s[k] = __ldcg(&g_h[cb][k]);
        __syncthreads();

        if (warp < 6) {
            const int rl = warp / 3, gate = warp % 3;
            const int row = cta * 2 + rl;
            const int gr  = gate * QG + row;
            const float* wr = wih + (size_t)gr * XIN;
            float acc = 0.0f, accb = 0.0f;
            for (int k = lane; k + 32 < XIN; k += 64) {         // 1088 = 17*64, exact
                acc  += wr[k]      * xin_s[k];
                accb += wr[k + 32] * xin_s[k + 32];
            }
            float acc2 = 0.0f;
            const float* wr2 = whh + (size_t)gr * QG;
            #pragma unroll
            for (int k = lane; k < QG; k += 32) acc2 += wr2[k] * h_s[k];
            acc  = wredsum(acc + accb);
            acc2 = wredsum(acc2);
            if (lane == 0) { gi_s[rl][gate] = acc + bih[gr]; gh_s[rl][gate] = acc2 + bhh[gr]; }
        }
        __syncthreads();
        if (tid < 2) {
            const int row = cta * 2 + tid;
            float r  = sigf(gi_s[tid][0] + gh_s[tid][0]);
            float z  = sigf(gi_s[tid][1] + gh_s[tid][1]);
            float nn = tanhf(gi_s[tid][2] + r * gh_s[tid][2]);
            __stcg(&g_h[nb][row], (1.0f - z) * nn + z * h_s[row]);
        }
        gbar(&g_bar1, tgt);

        // ---- stage 3: hid = relu(qhw @ concat(h2, fix, attv) + b) ----
        for (int k = tid; k < QG; k += NT) h_s[k] = __ldcg(&g_h[nb][k]);  // h2
        __syncthreads();
        {
            const int rl = warp >> 2, w4 = warp & 3;
            const int row = cta * 2 + rl;
            const float* wr = qhw + (size_t)row * HIN;
            float acc = 0.0f;
            for (int k = w4 * 32 + lane; k < HIN; k += 128) {
                float v = (k < QG) ? h_s[k] : xin_s[k - QG];  // fix @ xin[0..64), attv @ xin[64..576)
                acc += wr[k] * v;
            }
            acc = wredsum(acc);
            if (lane == 0) p3_s[rl][w4] = acc;
        }
        __syncthreads();
        if (tid < 2) {
            const int row = cta * 2 + tid;
            float s = p3_s[tid][0] + p3_s[tid][1] + p3_s[tid][2] + p3_s[tid][3] + qhb[row];
            __stcg(&g_hid[row], fmaxf(s, 0.0f));
        }
        gbar(&g_bar1, tgt);
    }

    // finals: query_n from last hid, q_gru_n = final h (in buffer T&1 == 0)
    if (cta < NH) {
        float acc = 0.0f;
        const float* wqc = wq + cta * 64 + j64;
        #pragma unroll 4
        for (int i = p64 * 64; i < p64 * 64 + 64; ++i)
            acc += __ldcg(&g_hid[i]) * wqc[(size_t)i * NHA];
        red_s[p64 * 64 + j64] = acc;
        __syncthreads();
        if (tid < 64)
            g_fin_q[cta * 64 + tid] = red_s[tid] + red_s[64 + tid] + red_s[128 + tid] + red_s[192 + tid];
    } else if (cta == NH) {
        if (tid < QG) g_fin_h[tid] = __ldcg(&g_h[T & 1][tid]);
    }
}

// ---------------- dec_att_a (parallel over t) ----------------
__global__ void __launch_bounds__(NT)
dec_atta_kernel(const float* __restrict__ x_att)
{
    const int t = blockIdx.x;
    const int src = (t >= HZ) ? (t - HZ) : 0;
    __shared__ float att_s[64 * 69];
    __shared__ float aw_s[NHA];
    const float* at = x_att + (size_t)t * N * A;
    for (int idx = threadIdx.x; idx < N * A; idx += NT)
        att_s[(idx >> 6) * 69 + (idx & 63)] = at[idx];
    for (int k = threadIdx.x; k < NHA; k += NT)
        aw_s[k] = g_attw[(size_t)src * NHA + k];
    __syncthreads();
    #pragma unroll
    for (int pass = 0; pass < 2; ++pass) {
        int o = pass * NT + threadIdx.x;
        int h = o >> 6, a = o & 63;
        float acc = 0.0f;
        #pragma unroll 8
        for (int n = 0; n < N; ++n) acc += aw_s[h * 64 + n] * att_s[n * 69 + a];
        g_dec_atta[t][o] = acc;
    }
}

// ---------------- phase 2: decoder GRU scan ----------------
__global__ void __launch_bounds__(NT, 1)
phase2_kernel(const float* __restrict__ x_fix,
              const float* __restrict__ wih, const float* __restrict__ whh,
              const float* __restrict__ bih, const float* __restrict__ bhh)
{
    const int tid  = threadIdx.x, cta = blockIdx.x;
    const int lane = tid & 31,    warp = tid >> 5;
    unsigned tgt = 0;
    __shared__ float xin_s[DXIN];
    __shared__ float h_s[DG];
    __shared__ float gi_s[2][3], gh_s[2][3];

    for (int t = 0; t < T; ++t) {
        for (int k = tid; k < DXIN; k += NT)
            xin_s[k] = (k < F) ? x_fix[t * F + k] : g_dec_atta[t][k - F];
        for (int k = tid; k < DG; k += NT)
            h_s[k] = (t > 0) ? __ldcg(&g_dec_gru[t - 1][k]) : 0.0f;
        __syncthreads();

        if (warp < 6) {
            const int rl = warp / 3, gate = warp % 3;
            const int row = cta * 2 + rl;
            const int gr  = gate * DG + row;
            const float* wr = wih + (size_t)gr * DXIN;
            float acc = 0.0f, accb = 0.0f;
            for (int k = lane; k + 32 < DXIN; k += 64) {        // 576 = 9*64, exact
                acc  += wr[k]      * xin_s[k];
                accb += wr[k + 32] * xin_s[k + 32];
            }
            float acc2 = 0.0f;
            const float* wr2 = whh + (size_t)gr * DG;
            #pragma unroll
            for (int k = lane; k < DG; k += 32) acc2 += wr2[k] * h_s[k];
            acc  = wredsum(acc + accb);
            acc2 = wredsum(acc2);
            if (lane == 0) { gi_s[rl][gate] = acc + bih[gr]; gh_s[rl][gate] = acc2 + bhh[gr]; }
        }
        __syncthreads();
        if (tid < 2) {
            const int row = cta * 2 + tid;
            float r  = sigf(gi_s[tid][0] + gh_s[tid][0]);
            float z  = sigf(gi_s[tid][1] + gh_s[tid][1]);
            float nn = tanhf(gi_s[tid][2] + r * gh_s[tid][2]);
            __stcg(&g_dec_gru[t][row], (1.0f - z) * nn + z * h_s[row]);
        }
        gbar(&g_bar2, tgt);
    }
    if (cta == 0 && tid < DG) g_fin_dec[tid] = __ldcg(&g_dec_gru[T - 1][tid]);
}

// ---------------- phase 3a: z_feat[t] = dec_hid_w[:, :832] @ feat[t] + b ----------------
__global__ void __launch_bounds__(NT)
zfeat_kernel(const float* __restrict__ x_fix,
             const float* __restrict__ dhw, const float* __restrict__ dhb)
{
    const int tid = threadIdx.x, lane = tid & 31, warp = tid >> 5;
    const int t0 = blockIdx.x * 8;
    __shared__ float f_s[8][HIN];   // 26.6 KB
    for (int idx = tid; idx < 8 * HIN; idx += NT) {
        int tt = idx / HIN, k = idx % HIN;
        int t = t0 + tt;
        float v;
        if (k < DG)           v = g_dec_gru[t][k];
        else if (k < DG + F)  v = x_fix[t * F + (k - DG)];
        else                  v = g_dec_atta[t][k - DG - F];
        f_s[tt][k] = v;
    }
    __syncthreads();
    for (int j = warp; j < DH; j += 8) {
        const float* wr = dhw + (size_t)j * DHIN;
        float acc[8];
        #pragma unroll
        for (int i = 0; i < 8; ++i) acc[i] = 0.0f;
        for (int k = lane; k < HIN; k += 32) {                  // 832 = 26*32, exact
            float w = wr[k];
            #pragma unroll
            for (int tt = 0; tt < 8; ++tt) acc[tt] += w * f_s[tt][k];
        }
        #pragma unroll
        for (int tt = 0; tt < 8; ++tt) {
            float s = wredsum(acc[tt]);
            if (lane == 0) g_zf[t0 + tt][j] = s + dhb[j];
        }
    }
}

// ---------------- phase 3b: per-(t,n) hid + pred ----------------
__global__ void __launch_bounds__(NT)
pred_kernel(const float* __restrict__ x_att,
            const float* __restrict__ dhw, const float* __restrict__ dow,
            const float* __restrict__ dob, float* __restrict__ out)
{
    extern __shared__ float sm[];
    float* Wa   = sm;                  // 256*65
    float* Wo   = Wa + 256 * 65;       // 64*257
    float* atts = Wo + 64 * 257;       // 64*69
    float* z_s  = atts + 64 * 69;      // 256
    float* hid_s = z_s + 256;          // 256
    float* bo_s  = hid_s + 256;        // 64
    float* red   = bo_s + 64;          // 256

    const int t = blockIdx.x, tid = threadIdx.x;
    for (int idx = tid; idx < 256 * 64; idx += NT) {
        int j = idx >> 6, a = idx & 63;
        Wa[j * 65 + a] = dhw[(size_t)j * DHIN + 832 + a];
    }
    for (int idx = tid; idx < 64 * 256; idx += NT) {
        int k = idx >> 8, j = idx & 255;
        Wo[k * 257 + j] = dow[k * 256 + j];
    }
    const float* at = x_att + (size_t)t * N * A;
    for (int idx = tid; idx < N * A; idx += NT)
        atts[(idx >> 6) * 69 + (idx & 63)] = at[idx];
    z_s[tid] = g_zf[t][tid];
    if (tid < 64) bo_s[tid] = dob[tid];
    __syncthreads();

    const int p = tid >> 6, kk = tid & 63;
    for (int n = 0; n < N; ++n) {
        {   // hid[j] for j = tid
            float a = z_s[tid];
            const float* wrow = Wa + tid * 65;
            const float* ar = atts + n * 69;
            #pragma unroll 8
            for (int c = 0; c < 64; ++c) a += wrow[c] * ar[c];
            hid_s[tid] = fmaxf(a, 0.0f);
        }
        __syncthreads();
        {   // pred partials: output kk, quarter p
            float acc = 0.0f;
            const float* wrow = Wo + kk * 257 + p * 64;
            const float* hr = hid_s + p * 64;
            #pragma unroll 8
            for (int c = 0; c < 64; ++c) acc += wrow[c] * hr[c];
            red[p * 64 + kk] = acc;
        }
        __syncthreads();
        if (tid < 64)
            out[((size_t)t * N + n) * A + tid] =
                fmaxf(red[tid] + red[64 + tid] + red[128 + tid] + red[192 + tid] + bo_s[tid], 0.0f);
        __syncthreads();
    }
}

// ---------------- finalize: copy secondary outputs with bounds guard ----------------
__global__ void finalize_kernel(float* __restrict__ out, int out_size)
{
    int i = blockIdx.x * NT + threadIdx.x;
    if (i < ATTW_SZ && (ATTW_OFF + i) < out_size)  out[ATTW_OFF + i]  = g_attw[i];
    if (i < QG      && (QGRU_OFF + i) < out_size)  out[QGRU_OFF + i]  = g_fin_h[i];
    if (i < DG      && (DECGRU_OFF + i) < out_size) out[DECGRU_OFF + i] = g_fin_dec[i];
    if (i < NHA     && (QN_OFF + i) < out_size)    out[QN_OFF + i]    = g_fin_q[i];
}

// ---------------- launch ----------------
extern "C" void kernel_launch(void* const* d_in, const int* in_sizes, int n_in,
                              void* d_out, int out_size)
{
    (void)in_sizes; (void)n_in;
    const float* x_fix = (const float*)d_in[0];
    const float* x_att = (const float*)d_in[1];
    // d_in[2] = train_horizon (constant 16, hardcoded)
    const float* qwih = (const float*)d_in[3];
    const float* qwhh = (const float*)d_in[4];
    const float* qbih = (const float*)d_in[5];
    const float* qbhh = (const float*)d_in[6];
    const float* qhw  = (const float*)d_in[7];
    const float* qhb  = (const float*)d_in[8];
    const float* wq   = (const float*)d_in[9];
    const float* dwih = (const float*)d_in[10];
    const float* dwhh = (const float*)d_in[11];
    const float* dbih = (const float*)d_in[12];
    const float* dbhh = (const float*)d_in[13];
    const float* dhw  = (const float*)d_in[14];
    const float* dhb  = (const float*)d_in[15];
    const float* dow  = (const float*)d_in[16];
    const float* dob  = (const float*)d_in[17];
    float* out = (float*)d_out;

    static_assert(QN_OFF + NHA == 9438208, "output layout");

    init_kernel<<<1, 512>>>();
    phase1_kernel<<<GRID1, NT>>>(x_fix, x_att, qwih, qwhh, qbih, qbhh, qhw, qhb, wq);
    dec_atta_kernel<<<T, NT>>>(x_att);
    phase2_kernel<<<GRID1, NT>>>(x_fix, dwih, dwhh, dbih, dbhh);
    zfeat_kernel<<<T / 8, NT>>>(x_fix, dhw, dhb);

    const int pred_smem = (256 * 65 + 64 * 257 + 64 * 69 + 256 + 256 + 64 + 256) * (int)sizeof(float);
    cudaFuncSetAttribute(pred_kernel, cudaFuncAttributeMaxDynamicSharedMemorySize, pred_smem);
    pred_kernel<<<T, NT, pred_smem>>>(x_att, dhw, dow, dob, out);

    finalize_kernel<<<(ATTW_SZ + NT - 1) / NT, NT>>>(out, out_size);
}

// round 17
// speedup vs baseline: 1.0279x; 1.0279x over previous
#include <cuda_runtime.h>
#include <math.h>

#define T 2048
#define N 64
#define F 64
#define A 64
#define NH 8
#define QG 256
#define QH 256
#define DG 256
#define DH 256
#define HZ 16

#define XIN  (F + 2*A*NH)        // 1088
#define HIN  (QG + F + A*NH)     // 832
#define DXIN (F + A*NH)          // 576
#define DHIN (DG + F + A*NH + A) // 896
#define NHA  (NH*A)              // 512

#define GRID1 128
#define NT 256

// output layout: pred, attw, q_gru_n, dec_gru_n, query_n (flattened concat)
#define PRED_SZ   (T*N*A)              // 8388608
#define ATTW_OFF  PRED_SZ
#define ATTW_SZ   (T*NH*N)             // 1048576
#define QGRU_OFF  (ATTW_OFF + ATTW_SZ)
#define DECGRU_OFF (QGRU_OFF + QG)
#define QN_OFF    (DECGRU_OFF + DG)

// ---------------- device scratch (static, allowed) ----------------
__device__ float g_h[2][QG];
__device__ float g_query[NHA];
__device__ float g_attv[NHA];
__device__ float g_hid[QH];
__device__ float g_attw[T * NHA];        // 4 MB
__device__ float g_dec_gru[T][DG];       // 2 MB
__device__ float g_dec_atta[T][NHA];     // 4 MB
__device__ float g_zf[T][DH];            // 2 MB
__device__ float g_fin_h[QG];
__device__ float g_fin_dec[DG];
__device__ float g_fin_q[NHA];
__device__ unsigned g_bar1;
__device__ unsigned g_bar2;

// ---------------- helpers ----------------
__device__ __forceinline__ float wredsum(float v) {
    #pragma unroll
    for (int o = 16; o; o >>= 1) v += __shfl_down_sync(0xffffffffu, v, o);
    return v;
}
__device__ __forceinline__ float sigf(float x) { return 1.0f / (1.0f + expf(-x)); }

// monotonic-counter grid barrier; all CTAs must be co-resident
__device__ __forceinline__ void gbar(unsigned* ctr, unsigned& tgt) {
    __syncthreads();
    if (threadIdx.x == 0) {
        __threadfence();
        atomicAdd(ctr, 1u);
        tgt += GRID1;
        while (*(volatile unsigned*)ctr < tgt) { }
    }
    __syncthreads();
}

// ---------------- init ----------------
__global__ void init_kernel() {
    int tid = threadIdx.x;
    if (tid == 0) { g_bar1 = 0u; g_bar2 = 0u; }
    if (tid < QG)  g_h[0][tid] = 0.0f;
    if (tid < NHA) g_query[tid] = 1.0f;
}

// ---------------- phase 1: recurrent query scan ----------------
__global__ void __launch_bounds__(NT, 1)
phase1_kernel(const float* __restrict__ x_fix, const float* __restrict__ x_att,
              const float* __restrict__ wih, const float* __restrict__ whh,
              const float* __restrict__ bih, const float* __restrict__ bhh,
              const float* __restrict__ qhw, const float* __restrict__ qhb,
              const float* __restrict__ wq)
{
    const int tid  = threadIdx.x, cta = blockIdx.x;
    const int lane = tid & 31,    warp = tid >> 5;
    unsigned tgt = 0;

    __shared__ float att_s[64 * 69];
    __shared__ float q_s[64], aw_s[64], red_s[4 * 64];
    __shared__ float sred[2];
    __shared__ float xin_s[XIN];
    __shared__ float h_s[QG];
    __shared__ float gi_s[2][3], gh_s[2][3];
    __shared__ float p3_s[2][4];

    const int p64 = tid >> 6, j64 = tid & 63;

    for (int t = 0; t < T; ++t) {
        const int cb = t & 1, nb = cb ^ 1;

        // ---- stage 1 (CTAs 0..7): query projection (t>0) + attention for head h ----
        if (cta < NH) {
            const int h = cta;
            const float* at = x_att + (size_t)t * N * A;
            for (int idx = tid; idx < N * A; idx += NT)
                att_s[(idx >> 6) * 69 + (idx & 63)] = at[idx];

            if (t > 0) {
                float acc = 0.0f;
                const float* wqc = wq + h * 64 + j64;
                #pragma unroll 4
                for (int i = p64 * 64; i < p64 * 64 + 64; ++i)
                    acc += __ldcg(&g_hid[i]) * wqc[(size_t)i * NHA];
                red_s[p64 * 64 + j64] = acc;
                __syncthreads();
                if (tid < 64) {
                    float q = red_s[tid] + red_s[64 + tid] + red_s[128 + tid] + red_s[192 + tid];
                    q_s[tid] = q;
                    __stcg(&g_query[h * 64 + tid], q);
                }
            } else {
                if (tid < 64) q_s[tid] = 1.0f;   // initial query = ones (g_query preset)
            }
            __syncthreads();

            // logits (scaled)
            if (tid < 64) {
                float l = 0.0f;
                const float* ar = att_s + tid * 69;
                #pragma unroll 8
                for (int a = 0; a < 64; ++a) l += q_s[a] * ar[a];
                red_s[tid] = l * 0.125f;
            }
            __syncthreads();
            if (tid < 32) {
                float m = fmaxf(red_s[tid], red_s[tid + 32]);
                #pragma unroll
                for (int o = 16; o; o >>= 1) m = fmaxf(m, __shfl_down_sync(0xffffffffu, m, o));
                if (tid == 0) sred[0] = m;
            }
            __syncthreads();
            if (tid < 64) aw_s[tid] = expf(red_s[tid] - sred[0]);
            __syncthreads();
            if (tid < 32) {
                float s = wredsum(aw_s[tid] + aw_s[tid + 32]);
                if (tid == 0) sred[1] = s;
            }
            __syncthreads();
            if (tid < 64) {
                float w = aw_s[tid] / sred[1];
                aw_s[tid] = w;
                g_attw[(size_t)t * NHA + h * 64 + tid] = w;
            }
            __syncthreads();
            // att_v[h, a]
            {
                float acc = 0.0f;
                #pragma unroll 4
                for (int n = p64 * 16; n < p64 * 16 + 16; ++n)
                    acc += aw_s[n] * att_s[n * 69 + j64];
                red_s[p64 * 64 + j64] = acc;
            }
            __syncthreads();
            if (tid < 64)
                __stcg(&g_attv[h * 64 + tid],
                       red_s[tid] + red_s[64 + tid] + red_s[128 + tid] + red_s[192 + tid]);
        }
        gbar(&g_bar1, tgt);

        // ---- stage 2: GRU (2 rows per CTA) ----
        for (int k = tid; k < XIN; k += NT) {
            float v;
            if (k < F)            v = x_fix[t * F + k];
            else if (k < F + NHA) v = __ldcg(&g_attv[k - F]);
            else                  v = __ldcg(&g_query[k - F - NHA]);
            xin_s[k] = v;
        }
        for (int k = tid; k < QG; k += NT) h_s[k] = __ldcg(&g_h[cb][k]);
        __syncthreads();

        if (warp < 6) {
            const int rl = warp / 3, gate = warp % 3;
            const int row = cta * 2 + rl;
            const int gr  = gate * QG + row;
            const float* wr = wih + (size_t)gr * XIN;
            float acc = 0.0f, accb = 0.0f;
            for (int k = lane; k + 32 < XIN; k += 64) {         // 1088 = 17*64, exact
                acc  += wr[k]      * xin_s[k];
                accb += wr[k + 32] * xin_s[k + 32];
            }
            float acc2 = 0.0f;
            const float* wr2 = whh + (size_t)gr * QG;
            #pragma unroll
            for (int k = lane; k < QG; k += 32) acc2 += wr2[k] * h_s[k];
            acc  = wredsum(acc + accb);
            acc2 = wredsum(acc2);
            if (lane == 0) { gi_s[rl][gate] = acc + bih[gr]; gh_s[rl][gate] = acc2 + bhh[gr]; }
        }
        __syncthreads();
        if (tid < 2) {
            const int row = cta * 2 + tid;
            float r  = sigf(gi_s[tid][0] + gh_s[tid][0]);
            float z  = sigf(gi_s[tid][1] + gh_s[tid][1]);
            float nn = tanhf(gi_s[tid][2] + r * gh_s[tid][2]);
            __stcg(&g_h[nb][row], (1.0f - z) * nn + z * h_s[row]);
        }
        gbar(&g_bar1, tgt);

        // ---- stage 3: hid = relu(qhw @ concat(h2, fix, attv) + b) ----
        for (int k = tid; k < QG; k += NT) h_s[k] = __ldcg(&g_h[nb][k]);  // h2
        __syncthreads();
        {
            const int rl = warp >> 2, w4 = warp & 3;
            const int row = cta * 2 + rl;
            const float* wr = qhw + (size_t)row * HIN;
            float acc = 0.0f;
            for (int k = w4 * 32 + lane; k < HIN; k += 128) {
                float v = (k < QG) ? h_s[k] : xin_s[k - QG];  // fix @ xin[0..64), attv @ xin[64..576)
                acc += wr[k] * v;
            }
            acc = wredsum(acc);
            if (lane == 0) p3_s[rl][w4] = acc;
        }
        __syncthreads();
        if (tid < 2) {
            const int row = cta * 2 + tid;
            float s = p3_s[tid][0] + p3_s[tid][1] + p3_s[tid][2] + p3_s[tid][3] + qhb[row];
            __stcg(&g_hid[row], fmaxf(s, 0.0f));
        }
        gbar(&g_bar1, tgt);
    }

    // finals: query_n from last hid, q_gru_n = final h (in buffer T&1 == 0)
    if (cta < NH) {
        float acc = 0.0f;
        const float* wqc = wq + cta * 64 + j64;
        #pragma unroll 4
        for (int i = p64 * 64; i < p64 * 64 + 64; ++i)
            acc += __ldcg(&g_hid[i]) * wqc[(size_t)i * NHA];
        red_s[p64 * 64 + j64] = acc;
        __syncthreads();
        if (tid < 64)
            g_fin_q[cta * 64 + tid] = red_s[tid] + red_s[64 + tid] + red_s[128 + tid] + red_s[192 + tid];
    } else if (cta == NH) {
        if (tid < QG) g_fin_h[tid] = __ldcg(&g_h[T & 1][tid]);
    }
}

// ---------------- dec_att_a (parallel over t) ----------------
__global__ void __launch_bounds__(NT)
dec_atta_kernel(const float* __restrict__ x_att)
{
    const int t = blockIdx.x;
    const int src = (t >= HZ) ? (t - HZ) : 0;
    __shared__ float att_s[64 * 69];
    __shared__ float aw_s[NHA];
    const float* at = x_att + (size_t)t * N * A;
    for (int idx = threadIdx.x; idx < N * A; idx += NT)
        att_s[(idx >> 6) * 69 + (idx & 63)] = at[idx];
    for (int k = threadIdx.x; k < NHA; k += NT)
        aw_s[k] = g_attw[(size_t)src * NHA + k];
    __syncthreads();
    #pragma unroll
    for (int pass = 0; pass < 2; ++pass) {
        int o = pass * NT + threadIdx.x;
        int h = o >> 6, a = o & 63;
        float acc = 0.0f;
        #pragma unroll 8
        for (int n = 0; n < N; ++n) acc += aw_s[h * 64 + n] * att_s[n * 69 + a];
        g_dec_atta[t][o] = acc;
    }
}

// ---------------- phase 2: decoder GRU scan ----------------
__global__ void __launch_bounds__(NT, 1)
phase2_kernel(const float* __restrict__ x_fix,
              const float* __restrict__ wih, const float* __restrict__ whh,
              const float* __restrict__ bih, const float* __restrict__ bhh)
{
    const int tid  = threadIdx.x, cta = blockIdx.x;
    const int lane = tid & 31,    warp = tid >> 5;
    unsigned tgt = 0;
    __shared__ float xin_s[DXIN];
    __shared__ float h_s[DG];
    __shared__ float gi_s[2][3], gh_s[2][3];

    for (int t = 0; t < T; ++t) {
        for (int k = tid; k < DXIN; k += NT)
            xin_s[k] = (k < F) ? x_fix[t * F + k] : g_dec_atta[t][k - F];
        for (int k = tid; k < DG; k += NT)
            h_s[k] = (t > 0) ? __ldcg(&g_dec_gru[t - 1][k]) : 0.0f;
        __syncthreads();

        if (warp < 6) {
            const int rl = warp / 3, gate = warp % 3;
            const int row = cta * 2 + rl;
            const int gr  = gate * DG + row;
            const float* wr = wih + (size_t)gr * DXIN;
            float acc = 0.0f, accb = 0.0f;
            for (int k = lane; k + 32 < DXIN; k += 64) {        // 576 = 9*64, exact
                acc  += wr[k]      * xin_s[k];
                accb += wr[k + 32] * xin_s[k + 32];
            }
            float acc2 = 0.0f;
            const float* wr2 = whh + (size_t)gr * DG;
            #pragma unroll
            for (int k = lane; k < DG; k += 32) acc2 += wr2[k] * h_s[k];
            acc  = wredsum(acc + accb);
            acc2 = wredsum(acc2);
            if (lane == 0) { gi_s[rl][gate] = acc + bih[gr]; gh_s[rl][gate] = acc2 + bhh[gr]; }
        }
        __syncthreads();
        if (tid < 2) {
            const int row = cta * 2 + tid;
            float r  = sigf(gi_s[tid][0] + gh_s[tid][0]);
            float z  = sigf(gi_s[tid][1] + gh_s[tid][1]);
            float nn = tanhf(gi_s[tid][2] + r * gh_s[tid][2]);
            __stcg(&g_dec_gru[t][row], (1.0f - z) * nn + z * h_s[row]);
        }
        gbar(&g_bar2, tgt);
    }
    if (cta == 0 && tid < DG) g_fin_dec[tid] = __ldcg(&g_dec_gru[T - 1][tid]);
}

// ---------------- phase 3a: z_feat[t] = dec_hid_w[:, :832] @ feat[t] + b ----------------
__global__ void __launch_bounds__(NT)
zfeat_kernel(const float* __restrict__ x_fix,
             const float* __restrict__ dhw, const float* __restrict__ dhb)
{
    const int tid = threadIdx.x, lane = tid & 31, warp = tid >> 5;
    const int t0 = blockIdx.x * 8;
    __shared__ float f_s[8][HIN];   // 26.6 KB
    for (int idx = tid; idx < 8 * HIN; idx += NT) {
        int tt = idx / HIN, k = idx % HIN;
        int t = t0 + tt;
        float v;
        if (k < DG)           v = g_dec_gru[t][k];
        else if (k < DG + F)  v = x_fix[t * F + (k - DG)];
        else                  v = g_dec_atta[t][k - DG - F];
        f_s[tt][k] = v;
    }
    __syncthreads();
    for (int j = warp; j < DH; j += 8) {
        const float* wr = dhw + (size_t)j * DHIN;
        float acc[8];
        #pragma unroll
        for (int i = 0; i < 8; ++i) acc[i] = 0.0f;
        for (int k = lane; k < HIN; k += 32) {                  // 832 = 26*32, exact
            float w = wr[k];
            #pragma unroll
            for (int tt = 0; tt < 8; ++tt) acc[tt] += w * f_s[tt][k];
        }
        #pragma unroll
        for (int tt = 0; tt < 8; ++tt) {
            float s = wredsum(acc[tt]);
            if (lane == 0) g_zf[t0 + tt][j] = s + dhb[j];
        }
    }
}

// ---------------- phase 3b: per-(t,n) hid + pred ----------------
__global__ void __launch_bounds__(NT)
pred_kernel(const float* __restrict__ x_att,
            const float* __restrict__ dhw, const float* __restrict__ dow,
            const float* __restrict__ dob, float* __restrict__ out)
{
    extern __shared__ float sm[];
    float* Wa   = sm;                  // 256*65
    float* Wo   = Wa + 256 * 65;       // 64*257
    float* atts = Wo + 64 * 257;       // 64*69
    float* z_s  = atts + 64 * 69;      // 256
    float* hid_s = z_s + 256;          // 256
    float* bo_s  = hid_s + 256;        // 64
    float* red   = bo_s + 64;          // 256

    const int t = blockIdx.x, tid = threadIdx.x;
    for (int idx = tid; idx < 256 * 64; idx += NT) {
        int j = idx >> 6, a = idx & 63;
        Wa[j * 65 + a] = dhw[(size_t)j * DHIN + 832 + a];
    }
    for (int idx = tid; idx < 64 * 256; idx += NT) {
        int k = idx >> 8, j = idx & 255;
        Wo[k * 257 + j] = dow[k * 256 + j];
    }
    const float* at = x_att + (size_t)t * N * A;
    for (int idx = tid; idx < N * A; idx += NT)
        atts[(idx >> 6) * 69 + (idx & 63)] = at[idx];
    z_s[tid] = g_zf[t][tid];
    if (tid < 64) bo_s[tid] = dob[tid];
    __syncthreads();

    const int p = tid >> 6, kk = tid & 63;
    for (int n = 0; n < N; ++n) {
        {   // hid[j] for j = tid
            float a = z_s[tid];
            const float* wrow = Wa + tid * 65;
            const float* ar = atts + n * 69;
            #pragma unroll 8
            for (int c = 0; c < 64; ++c) a += wrow[c] * ar[c];
            hid_s[tid] = fmaxf(a, 0.0f);
        }
        __syncthreads();
        {   // pred partials: output kk, quarter p
            float acc = 0.0f;
            const float* wrow = Wo + kk * 257 + p * 64;
            const float* hr = hid_s + p * 64;
            #pragma unroll 8
            for (int c = 0; c < 64; ++c) acc += wrow[c] * hr[c];
            red[p * 64 + kk] = acc;
        }
        __syncthreads();
        if (tid < 64)
            out[((size_t)t * N + n) * A + tid] =
                fmaxf(red[tid] + red[64 + tid] + red[128 + tid] + red[192 + tid] + bo_s[tid], 0.0f);
        __syncthreads();
    }
}

// ---------------- finalize: copy secondary outputs with bounds guard ----------------
__global__ void finalize_kernel(float* __restrict__ out, int out_size)
{
    int i = blockIdx.x * NT + threadIdx.x;
    if (i < ATTW_SZ && (ATTW_OFF + i) < out_size)  out[ATTW_OFF + i]  = g_attw[i];
    if (i < QG      && (QGRU_OFF + i) < out_size)  out[QGRU_OFF + i]  = g_fin_h[i];
    if (i < DG      && (DECGRU_OFF + i) < out_size) out[DECGRU_OFF + i] = g_fin_dec[i];
    if (i < NHA     && (QN_OFF + i) < out_size)    out[QN_OFF + i]    = g_fin_q[i];
}

// ---------------- launch ----------------
extern "C" void kernel_launch(void* const* d_in, const int* in_sizes, int n_in,
                              void* d_out, int out_size)
{
    (void)in_sizes; (void)n_in;
    const float* x_fix = (const float*)d_in[0];
    const float* x_att = (const float*)d_in[1];
    // d_in[2] = train_horizon (constant 16, hardcoded)
    const float* qwih = (const float*)d_in[3];
    const float* qwhh = (const float*)d_in[4];
    const float* qbih = (const float*)d_in[5];
    const float* qbhh = (const float*)d_in[6];
    const float* qhw  = (const float*)d_in[7];
    const float* qhb  = (const float*)d_in[8];
    const float* wq   = (const float*)d_in[9];
    const float* dwih = (const float*)d_in[10];
    const float* dwhh = (const float*)d_in[11];
    const float* dbih = (const float*)d_in[12];
    const float* dbhh = (const float*)d_in[13];
    const float* dhw  = (const float*)d_in[14];
    const float* dhb  = (const float*)d_in[15];
    const float* dow  = (const float*)d_in[16];
    const float* dob  = (const float*)d_in[17];
    float* out = (float*)d_out;

    static_assert(QN_OFF + NHA == 9438208, "output layout");

    init_kernel<<<1, 512>>>();
    phase1_kernel<<<GRID1, NT>>>(x_fix, x_att, qwih, qwhh, qbih, qbhh, qhw, qhb, wq);
    dec_atta_kernel<<<T, NT>>>(x_att);
    phase2_kernel<<<GRID1, NT>>>(x_fix, dwih, dwhh, dbih, dbhh);
    zfeat_kernel<<<T / 8, NT>>>(x_fix, dhw, dhb);

    const int pred_smem = (256 * 65 + 64 * 257 + 64 * 69 + 256 + 256 + 64 + 256) * (int)sizeof(float);
    cudaFuncSetAttribute(pred_kernel, cudaFuncAttributeMaxDynamicSharedMemorySize, pred_smem);
    pred_kernel<<<T, NT, pred_smem>>>(x_att, dhw, dow, dob, out);

    finalize_kernel<<<(ATTW_SZ + NT - 1) / NT, NT>>>(out, out_size);
}